// round 13
// baseline (speedup 1.0000x reference)
#include <cuda_runtime.h>
#include <cuda_fp16.h>
#include <cstdint>

#define Bn 16
#define Cc 128
#define Hh 64
#define Ww 64

// ---- scratch ----
// g_wh: W fp16 A-fragment-vector layout, uint4[b][chunk8][tap9][cb8][r8][c4]
// g_xh: X fp16 pair-interleaved uint4[b][chunk8][pp4][h64][seg32].
__device__ uint4 g_wh[(size_t)Bn * 8 * 9 * 8 * 8 * 4];
__device__ uint4 g_xh[(size_t)Bn * 8 * 4 * 64 * 32];

__device__ __forceinline__ uint32_t h2(float a, float b) {
    __half2 h = __floats2half2_rn(a, b);
    return *(uint32_t*)&h;
}

// ---- fused prep: blocks [0,128) = W smem-transpose; [128, 1152) = X pack ----
__global__ void prep_all(const float* __restrict__ w, const float* __restrict__ x) {
    extern __shared__ float s[];            // W blocks: [16 co][1152]
    if (blockIdx.x < 128) {
        const int b  = blockIdx.x >> 3;
        const int cb = blockIdx.x & 7;
        const float* src = w + ((size_t)b * Cc + cb * 16) * 1152;
#pragma unroll
        for (int it = 0; it < 9; it++) {
            int idx = threadIdx.x + it * 512;   // 4608 uint4
            ((uint4*)s)[idx] = ((const uint4*)src)[idx];
        }
        __syncthreads();
#pragma unroll
        for (int it = 0; it < 5; it++) {
            int idx = threadIdx.x + it * 512;   // 2304 outputs
            if (idx < 2304) {
                int c    = idx & 3;
                int r    = (idx >> 2) & 7;
                int rest = idx >> 5;
                int t    = rest % 9;
                int ch   = rest / 9;            // 0..7
                int k0   = ch * 16 + 2 * c;
                uint4 o;
                o.x = h2(s[ r      * 1152 + (k0    ) * 9 + t], s[ r      * 1152 + (k0 + 1) * 9 + t]);
                o.y = h2(s[(r + 8) * 1152 + (k0    ) * 9 + t], s[(r + 8) * 1152 + (k0 + 1) * 9 + t]);
                o.z = h2(s[ r      * 1152 + (k0 + 8) * 9 + t], s[ r      * 1152 + (k0 + 9) * 9 + t]);
                o.w = h2(s[(r + 8) * 1152 + (k0 + 8) * 9 + t], s[(r + 8) * 1152 + (k0 + 9) * 9 + t]);
                g_wh[((((size_t)(b * 8 + ch) * 9 + t) * 8 + cb) * 8 + r) * 4 + c] = o;
            }
        }
    } else {
        int v    = (blockIdx.x - 128) * 512 + threadIdx.x;  // 524288
        int seg2 = v & 15;
        int h    = (v >> 4) & 63;
        int pp   = (v >> 10) & 3;
        int ch   = (v >> 12) & 7;
        int b    = v >> 15;
        int ci0  = ch * 16 + 2 * pp;
        int w0   = seg2 * 4;
        const float* base = x + ((size_t)(b * Cc + ci0) * Hh + h) * Ww + w0;
        float4 f0 = *(const float4*)(base);
        float4 f1 = *(const float4*)(base +     Hh * Ww);
        float4 f8 = *(const float4*)(base + 8 * Hh * Ww);
        float4 f9 = *(const float4*)(base + 9 * Hh * Ww);
        uint4 o0, o1;
        o0.x = h2(f0.x, f1.x);  o0.y = h2(f8.x, f9.x);
        o0.z = h2(f0.y, f1.y);  o0.w = h2(f8.y, f9.y);
        o1.x = h2(f0.z, f1.z);  o1.y = h2(f8.z, f9.z);
        o1.z = h2(f0.w, f1.w);  o1.w = h2(f8.w, f9.w);
        size_t oi = ((((size_t)(b * 8 + ch) * 4 + pp) * 64 + h) * 32) + 2 * seg2;
        g_xh[oi]     = o0;
        g_xh[oi + 1] = o1;
    }
}

// ---- main kernel: 4 warps of 64x64, 2 CTA/SM, TRIPLE-buffered 3-stage pipeline ----
// CTA = M=64 (one co half) x N=256 (4 rows x 64 w); 8 K-chunks of 16 ci, m16n8k16 fp16.
// X tile [4 pp][6 rows][76 slots][2 u32]; pair stride XP=936 u32, row stride 152,
// w=0 at slot 4. W tile: 1152 uint4 = this CTA's co-half of a g_wh chunk.
#define XP 936
#define XR 152
#define XBUF_F (4 * XP)     // 3744 u32 = 14976 B
#define WBUF_U4 1152        // 18432 B

__device__ __forceinline__ uint32_t s2u(const void* p) {
    uint32_t a;
    asm("{ .reg .u64 t; cvta.to.shared.u64 t, %1; cvt.u32.u64 %0, t; }" : "=r"(a) : "l"(p));
    return a;
}

#define CP16(dst_u32, src_ptr) \
    asm volatile("cp.async.cg.shared.global [%0], [%1], 16;" :: "r"(dst_u32), "l"(src_ptr))

#define MMA_F16(c, a0, a1, a2, a3, b0v, b1v)                                      \
    asm volatile("mma.sync.aligned.m16n8k16.row.col.f32.f16.f16.f32 "             \
                 "{%0,%1,%2,%3}, {%4,%5,%6,%7}, {%8,%9}, {%0,%1,%2,%3};"          \
                 : "+f"((c)[0]), "+f"((c)[1]), "+f"((c)[2]), "+f"((c)[3])         \
                 : "r"(a0), "r"(a1), "r"(a2), "r"(a3), "r"(b0v), "r"(b1v))

__global__ __launch_bounds__(128, 2)
void resconv_mma(const float* __restrict__ inp, float* __restrict__ out)
{
    extern __shared__ float smf[];
    uint32_t* smu = (uint32_t*)smf;

    const int tid  = threadIdx.x;
    const int lane = tid & 31;
    const int wid  = tid >> 5;       // 0..3 : output row within tile
    const int lr   = lane >> 2;      // 0..7
    const int lc   = lane & 3;       // 0..3

    const int h0  = blockIdx.x * 4;
    const int b   = blockIdx.y;
    const int wmH = blockIdx.z;      // co half of this CTA

    const uint32_t sbase = s2u(smf);
    const uint4* wsrc = g_wh + (size_t)b * 8 * 2304;

    // zero the 3 X buffers once (halo zeros are loop-invariant)
    for (int i = tid; i < 3 * XBUF_F; i += 128) smf[i] = 0.f;
    __syncthreads();

    float acc[4][8][4];
#pragma unroll
    for (int i = 0; i < 4; i++)
#pragma unroll
        for (int j = 0; j < 8; j++)
#pragma unroll
            for (int k = 0; k < 4; k++) acc[i][j][k] = 0.f;

    auto stageX = [&](int chunk, int xoff) {
#pragma unroll
        for (int it = 0; it < 6; it++) {
            int idx = tid + it * 128;            // [pp 4][row 6][seg 32] = 768
            int pr  = idx / 192;
            int rem = idx - pr * 192;
            int row = rem >> 5;
            int seg = rem & 31;
            int gh  = h0 + row - 1;
            if ((unsigned)gh < (unsigned)Hh) {
                const uint4* src = g_xh +
                    ((((size_t)b * 8 + chunk) * 4 + pr) * 64 + gh) * 32 + seg;
                uint32_t dst = sbase + 4u * (uint32_t)(xoff + pr * XP + row * XR + 8 + seg * 4);
                CP16(dst, src);
            }
        }
    };
    auto stageW = [&](int chunk, uint32_t woff_b) {
        const uint4* src = wsrc + (size_t)chunk * 2304;
#pragma unroll
        for (int it = 0; it < 9; it++) {
            int idx  = tid + it * 128;           // 0..1151
            int tap  = idx >> 7;
            int rest = idx & 127;
            CP16(sbase + woff_b + idx * 16u, src + tap * 256 + wmH * 128 + rest);
        }
    };

    const uint32_t WBASE = 3 * XBUF_F * 4;       // byte offset of W buffers

    // prologue: stage chunks 0 and 1 as two groups
    stageX(0, 0);
    stageW(0, WBASE);
    asm volatile("cp.async.commit_group;" ::: "memory");
    stageX(1, XBUF_F);
    stageW(1, WBASE + WBUF_U4 * 16);
    asm volatile("cp.async.commit_group;" ::: "memory");

    for (int kc = 0; kc < 8; kc++) {
        const int cur = kc % 3;
        const int xoff = cur * XBUF_F;
        const uint4* wbuf = (const uint4*)((const char*)smf + WBASE + cur * (WBUF_U4 * 16));

        // ensure group kc has landed (it has a full chunk of slack); kc+1 may fly
        if (kc < 7) {
            asm volatile("cp.async.wait_group 1;" ::: "memory");
        } else {
            asm volatile("cp.async.wait_group 0;" ::: "memory");
        }
        __syncthreads();   // also frees buffer (kc+2)%3 == (kc-1)%3 consumed last chunk

        // stage chunk kc+2 early — ~1.9 chunks of slack before it is waited on
        if (kc < 6) {
            const int nxt = (kc + 2) % 3;
            stageX(kc + 2, nxt * XBUF_F);
            stageW(kc + 2, WBASE + nxt * (WBUF_U4 * 16));
            asm volatile("cp.async.commit_group;" ::: "memory");
        }

        const uint32_t* xwarp = smu + xoff + lc * XP + wid * XR + (lr + 3) * 2;

#pragma unroll
        for (int t = 0; t < 9; t++) {
            const int kh = t / 3;
            const int kw = t - kh * 3;

            uint4 a[4];
#pragma unroll
            for (int tm = 0; tm < 4; tm++)
                a[tm] = wbuf[t * 128 + tm * 32 + lr * 4 + lc];

            const uint32_t* xq = xwarp + kh * XR + kw * 2;
            uint2 bb[8];
#pragma unroll
            for (int tn = 0; tn < 8; tn++)
                bb[tn] = *(const uint2*)(xq + tn * 16);

#pragma unroll
            for (int tn = 0; tn < 8; tn++)
#pragma unroll
                for (int tm = 0; tm < 4; tm++)
                    MMA_F16(acc[tm][tn], a[tm].x, a[tm].y, a[tm].z, a[tm].w,
                            bb[tn].x, bb[tn].y);
        }
    }

    // epilogue: out = inp + conv  (this warp: row h0+wid, all 64 w, this co-half)
    const int h = h0 + wid;
#pragma unroll
    for (int tm = 0; tm < 4; tm++) {
#pragma unroll
        for (int tn = 0; tn < 8; tn++) {
            const int w = tn * 8 + lc * 2;
            const int co0 = wmH * 64 + tm * 16 + lr;
#pragma unroll
            for (int half = 0; half < 2; half++) {
                const int co = co0 + half * 8;
                const size_t off = ((size_t)(b * Cc + co) * Hh + h) * Ww + w;
                float2 rv = *(const float2*)(inp + off);
                float2 ov;
                ov.x = rv.x + acc[tm][tn][half * 2 + 0];
                ov.y = rv.y + acc[tm][tn][half * 2 + 1];
                *(float2*)(out + off) = ov;
            }
        }
    }
}

extern "C" void kernel_launch(void* const* d_in, const int* in_sizes, int n_in,
                              void* d_out, int out_size)
{
    const float* inp = (const float*)d_in[0];   // [16,128,64,64]
    const float* wgt = (const float*)d_in[1];   // [16,128,128,3,3]
    float* out = (float*)d_out;

    cudaFuncSetAttribute(prep_all, cudaFuncAttributeMaxDynamicSharedMemorySize, 73728);
    prep_all<<<128 + 1024, 512, 73728>>>(wgt, inp);

    const int smem_bytes = 3 * XBUF_F * 4 + 3 * WBUF_U4 * 16;   // 44928 + 55296 = 100224
    cudaFuncSetAttribute(resconv_mma, cudaFuncAttributeMaxDynamicSharedMemorySize, smem_bytes);
    dim3 grid(Hh / 4, Bn, 2);   // (16, 16, 2) = 512 CTAs, 2/SM
    resconv_mma<<<grid, 128, smem_bytes>>>(inp, out);
}

// round 14
// speedup vs baseline: 1.0602x; 1.0602x over previous
#include <cuda_runtime.h>
#include <cuda_fp16.h>
#include <cstdint>

#define Bn 16
#define Cc 128
#define Hh 64
#define Ww 64

// ---- scratch ----
// g_wh: W fp16 A-fragment-vector layout, uint4[b][chunk8][tap9][cb8][r8][c4]
// g_xh: X fp16 pair-interleaved uint4[b][chunk8][pp4][h64][seg32].
__device__ uint4 g_wh[(size_t)Bn * 8 * 9 * 8 * 8 * 4];
__device__ uint4 g_xh[(size_t)Bn * 8 * 4 * 64 * 32];

__device__ __forceinline__ uint32_t h2(float a, float b) {
    __half2 h = __floats2half2_rn(a, b);
    return *(uint32_t*)&h;
}

// ---- fused prep: blocks [0,128) = W smem-transpose; [128, 1152) = X pack ----
// W smem rows padded to 1164 floats (==12 mod 32): transpose-read banks (12r+18c)%32
// are 2-way instead of 8-way conflicted.
#define WPREP_P  1164
#define WPREP_P4 291
__global__ void prep_all(const float* __restrict__ w, const float* __restrict__ x) {
    extern __shared__ float s[];            // W blocks: [16 co][1164]
    if (blockIdx.x < 128) {
        const int b  = blockIdx.x >> 3;
        const int cb = blockIdx.x & 7;
        const float* src = w + ((size_t)b * Cc + cb * 16) * 1152;
#pragma unroll
        for (int it = 0; it < 9; it++) {
            int idx = threadIdx.x + it * 512;   // 4608 uint4
            int row = idx / 288;
            int col = idx - row * 288;
            ((uint4*)s)[row * WPREP_P4 + col] = ((const uint4*)src)[idx];
        }
        __syncthreads();
#pragma unroll
        for (int it = 0; it < 5; it++) {
            int idx = threadIdx.x + it * 512;   // 2304 outputs
            if (idx < 2304) {
                int c    = idx & 3;
                int r    = (idx >> 2) & 7;
                int rest = idx >> 5;
                int t    = rest % 9;
                int ch   = rest / 9;            // 0..7
                int k0   = ch * 16 + 2 * c;
                uint4 o;
                o.x = h2(s[ r      * WPREP_P + (k0    ) * 9 + t], s[ r      * WPREP_P + (k0 + 1) * 9 + t]);
                o.y = h2(s[(r + 8) * WPREP_P + (k0    ) * 9 + t], s[(r + 8) * WPREP_P + (k0 + 1) * 9 + t]);
                o.z = h2(s[ r      * WPREP_P + (k0 + 8) * 9 + t], s[ r      * WPREP_P + (k0 + 9) * 9 + t]);
                o.w = h2(s[(r + 8) * WPREP_P + (k0 + 8) * 9 + t], s[(r + 8) * WPREP_P + (k0 + 9) * 9 + t]);
                g_wh[((((size_t)(b * 8 + ch) * 9 + t) * 8 + cb) * 8 + r) * 4 + c] = o;
            }
        }
    } else {
        int v    = (blockIdx.x - 128) * 512 + threadIdx.x;  // 524288
        int seg2 = v & 15;
        int h    = (v >> 4) & 63;
        int pp   = (v >> 10) & 3;
        int ch   = (v >> 12) & 7;
        int b    = v >> 15;
        int ci0  = ch * 16 + 2 * pp;
        int w0   = seg2 * 4;
        const float* base = x + ((size_t)(b * Cc + ci0) * Hh + h) * Ww + w0;
        float4 f0 = *(const float4*)(base);
        float4 f1 = *(const float4*)(base +     Hh * Ww);
        float4 f8 = *(const float4*)(base + 8 * Hh * Ww);
        float4 f9 = *(const float4*)(base + 9 * Hh * Ww);
        uint4 o0, o1;
        o0.x = h2(f0.x, f1.x);  o0.y = h2(f8.x, f9.x);
        o0.z = h2(f0.y, f1.y);  o0.w = h2(f8.y, f9.y);
        o1.x = h2(f0.z, f1.z);  o1.y = h2(f8.z, f9.z);
        o1.z = h2(f0.w, f1.w);  o1.w = h2(f8.w, f9.w);
        size_t oi = ((((size_t)(b * 8 + ch) * 4 + pp) * 64 + h) * 32) + 2 * seg2;
        g_xh[oi]     = o0;
        g_xh[oi + 1] = o1;
    }
}

// ---- main kernel (round-12 config: 4 warps of 64x64, 2 CTA/SM, double buffer) ----
// M-split: CTA = M=64 (one co half) x N=256 (4 rows x 64 w), 4 warps, warp tile 64x64,
// 128 threads, 2 CTAs/SM. 8 K-chunks of 16 ci, m16n8k16 fp16 MMA.
// X tile [4 pp][6 rows][76 slots][2 u32]; pair stride XP=936 u32 (==8 mod 32 -> conflict-free
// LDS.64 B-frags), row stride 152, w=0 at slot 4; each u32 = fp16x2 ci-pair.
// W tile: 1152 uint4/buffer = this CTA's co-half of a g_wh chunk ([tap9][cb4][r8][c4]).
#define XP 936
#define XR 152
#define XBUF_F (4 * XP)     // 3744 u32
#define WBUF_U4 1152

__device__ __forceinline__ uint32_t s2u(const void* p) {
    uint32_t a;
    asm("{ .reg .u64 t; cvta.to.shared.u64 t, %1; cvt.u32.u64 %0, t; }" : "=r"(a) : "l"(p));
    return a;
}

#define CP16(dst_u32, src_ptr) \
    asm volatile("cp.async.cg.shared.global [%0], [%1], 16;" :: "r"(dst_u32), "l"(src_ptr))

#define MMA_F16(c, a0, a1, a2, a3, b0v, b1v)                                      \
    asm volatile("mma.sync.aligned.m16n8k16.row.col.f32.f16.f16.f32 "             \
                 "{%0,%1,%2,%3}, {%4,%5,%6,%7}, {%8,%9}, {%0,%1,%2,%3};"          \
                 : "+f"((c)[0]), "+f"((c)[1]), "+f"((c)[2]), "+f"((c)[3])         \
                 : "r"(a0), "r"(a1), "r"(a2), "r"(a3), "r"(b0v), "r"(b1v))

__global__ __launch_bounds__(128, 2)
void resconv_mma(const float* __restrict__ inp, float* __restrict__ out)
{
    extern __shared__ float smf[];
    uint32_t* smu = (uint32_t*)smf;

    const int tid  = threadIdx.x;
    const int lane = tid & 31;
    const int wid  = tid >> 5;       // 0..3 : output row within tile
    const int lr   = lane >> 2;      // 0..7
    const int lc   = lane & 3;       // 0..3

    const int h0  = blockIdx.x * 4;
    const int b   = blockIdx.y;
    const int wmH = blockIdx.z;      // co half of this CTA

    const uint32_t sbase = s2u(smf);
    const uint4* wsrc = g_wh + (size_t)b * 8 * 2304;   // full-chunk stride = 2304 uint4

    // zero X buffers once (halo zeros are loop-invariant)
    for (int i = tid; i < 2 * XBUF_F; i += 128) smf[i] = 0.f;
    __syncthreads();

    float acc[4][8][4];
#pragma unroll
    for (int i = 0; i < 4; i++)
#pragma unroll
        for (int j = 0; j < 8; j++)
#pragma unroll
            for (int k = 0; k < 4; k++) acc[i][j][k] = 0.f;

    auto stageX = [&](int chunk, int xoff) {
#pragma unroll
        for (int it = 0; it < 6; it++) {
            int idx = tid + it * 128;            // [pp 4][row 6][seg 32] = 768
            int pr  = idx / 192;
            int rem = idx - pr * 192;
            int row = rem >> 5;
            int seg = rem & 31;
            int gh  = h0 + row - 1;
            if ((unsigned)gh < (unsigned)Hh) {
                const uint4* src = g_xh +
                    ((((size_t)b * 8 + chunk) * 4 + pr) * 64 + gh) * 32 + seg;
                uint32_t dst = sbase + 4u * (uint32_t)(xoff + pr * XP + row * XR + 8 + seg * 4);
                CP16(dst, src);
            }
        }
    };
    auto stageW = [&](int chunk, uint32_t woff_b) {
        const uint4* src = wsrc + (size_t)chunk * 2304;
#pragma unroll
        for (int it = 0; it < 9; it++) {
            int idx  = tid + it * 128;           // 0..1151
            int tap  = idx >> 7;
            int rest = idx & 127;                // cb4 x r8 x c4 within this co-half
            CP16(sbase + woff_b + idx * 16u, src + tap * 256 + wmH * 128 + rest);
        }
        asm volatile("cp.async.commit_group;" ::: "memory");
    };

    const uint32_t WBASE = 2 * XBUF_F * 4;       // byte offset of W buffers

    stageX(0, 0);
    stageW(0, WBASE);
    asm volatile("cp.async.wait_group 0;" ::: "memory");
    __syncthreads();

    for (int kc = 0; kc < 8; kc++) {
        const int cur = kc & 1;
        const int xoff = cur * XBUF_F;
        const uint4* wbuf = (const uint4*)((const char*)smf + WBASE + cur * (WBUF_U4 * 16));

        if (kc < 7) {
            stageX(kc + 1, (cur ^ 1) * XBUF_F);
            stageW(kc + 1, WBASE + (cur ^ 1) * (WBUF_U4 * 16));
        }

        const uint32_t* xwarp = smu + xoff + lc * XP + wid * XR + (lr + 3) * 2;

#pragma unroll
        for (int t = 0; t < 9; t++) {            // compile-time taps: immediate offsets
            const int kh = t / 3;
            const int kw = t - kh * 3;

            uint4 a[4];
#pragma unroll
            for (int tm = 0; tm < 4; tm++)
                a[tm] = wbuf[t * 128 + tm * 32 + lr * 4 + lc];

            const uint32_t* xq = xwarp + kh * XR + kw * 2;
            uint2 bb[8];
#pragma unroll
            for (int tn = 0; tn < 8; tn++)
                bb[tn] = *(const uint2*)(xq + tn * 16);

#pragma unroll
            for (int tn = 0; tn < 8; tn++)
#pragma unroll
                for (int tm = 0; tm < 4; tm++)
                    MMA_F16(acc[tm][tn], a[tm].x, a[tm].y, a[tm].z, a[tm].w,
                            bb[tn].x, bb[tn].y);
        }

        asm volatile("cp.async.wait_group 0;" ::: "memory");
        __syncthreads();
    }

    // epilogue: out = inp + conv  (this warp: row h0+wid, all 64 w, this co-half)
    const int h = h0 + wid;
#pragma unroll
    for (int tm = 0; tm < 4; tm++) {
#pragma unroll
        for (int tn = 0; tn < 8; tn++) {
            const int w = tn * 8 + lc * 2;
            const int co0 = wmH * 64 + tm * 16 + lr;
#pragma unroll
            for (int half = 0; half < 2; half++) {
                const int co = co0 + half * 8;
                const size_t off = ((size_t)(b * Cc + co) * Hh + h) * Ww + w;
                float2 rv = *(const float2*)(inp + off);
                float2 ov;
                ov.x = rv.x + acc[tm][tn][half * 2 + 0];
                ov.y = rv.y + acc[tm][tn][half * 2 + 1];
                *(float2*)(out + off) = ov;
            }
        }
    }
}

extern "C" void kernel_launch(void* const* d_in, const int* in_sizes, int n_in,
                              void* d_out, int out_size)
{
    const float* inp = (const float*)d_in[0];   // [16,128,64,64]
    const float* wgt = (const float*)d_in[1];   // [16,128,128,3,3]
    float* out = (float*)d_out;

    const int wprep_smem = 16 * WPREP_P * 4;    // 74496
    cudaFuncSetAttribute(prep_all, cudaFuncAttributeMaxDynamicSharedMemorySize, wprep_smem);
    prep_all<<<128 + 1024, 512, wprep_smem>>>(wgt, inp);

    const int smem_bytes = 2 * XBUF_F * 4 + 2 * WBUF_U4 * 16;   // 29952 + 36864 = 66816
    cudaFuncSetAttribute(resconv_mma, cudaFuncAttributeMaxDynamicSharedMemorySize, smem_bytes);
    dim3 grid(Hh / 4, Bn, 2);   // (16, 16, 2) = 512 CTAs, 2/SM
    resconv_mma<<<grid, 128, smem_bytes>>>(inp, out);
}